// round 2
// baseline (speedup 1.0000x reference)
#include <cuda_runtime.h>

#define NN 100000
#define EE 1600000
#define TOTE (NN + EE)

// ---------------- static device scratch (allocation-free) ----------------
__device__ int                g_rowptr[NN + 1];
__device__ int                g_cnt[NN];          // histogram, then cursor
__device__ float              g_dis[NN];          // rsqrt(deg)
__device__ float              g_ax[NN];           // (A_hat x)  per node
__device__ float              g_aone[NN];         // (A_hat 1)  per node
__device__ unsigned long long g_edge[TOTE];       // packed {src(int32) | normbits<<32}
__device__ float              g_bufA[NN * 32];    // carry h (26 used, padded)
__device__ float              g_bufB[NN * 32];
__device__ float              g_bufC[NN * 32];

__device__ __forceinline__ unsigned long long pack_edge(int c, float w) {
    return (unsigned long long)(unsigned)c |
           ((unsigned long long)__float_as_uint(w) << 32);
}

// ---------------- preprocessing ----------------
__global__ void k_init(int n) {
    int i = blockIdx.x * blockDim.x + threadIdx.x;
    if (i < n) g_cnt[i] = 1;   // self-loop
}

__global__ void k_hist(const int* __restrict__ ei, int E) {
    int e = blockIdx.x * blockDim.x + threadIdx.x;
    if (e < E) {
        int d = ei[E + e];
        atomicAdd(&g_cnt[d], 1);
    }
}

// single-block exclusive scan of g_cnt -> g_rowptr  (n ~ 100k, ~100 chunks)
__global__ void k_scan(int n) {
    __shared__ int sh[1024];
    __shared__ int soff;
    int tid = threadIdx.x;
    if (tid == 0) soff = 0;
    __syncthreads();
    for (int base = 0; base < n; base += 1024) {
        int i = base + tid;
        int v = (i < n) ? g_cnt[i] : 0;
        sh[tid] = v;
        __syncthreads();
        for (int d = 1; d < 1024; d <<= 1) {
            int t = (tid >= d) ? sh[tid - d] : 0;
            __syncthreads();
            sh[tid] += t;
            __syncthreads();
        }
        int off = soff;
        if (i < n) g_rowptr[i] = off + sh[tid] - v;   // exclusive
        __syncthreads();
        if (tid == 1023) soff = off + sh[1023];
        __syncthreads();
    }
    if (tid == 0) g_rowptr[n] = soff;
}

__global__ void k_selfloop(int n) {
    int i = blockIdx.x * blockDim.x + threadIdx.x;
    if (i < n) {
        float dv = rsqrtf((float)g_cnt[i]);
        g_dis[i] = dv;
        int p = g_rowptr[i];
        g_edge[p] = pack_edge(i, dv * dv);
        g_cnt[i] = p + 1;     // cursor
    }
}

__global__ void k_scatter(const int* __restrict__ ei, int E) {
    int e = blockIdx.x * blockDim.x + threadIdx.x;
    if (e < E) {
        int s = ei[e];
        int d = ei[E + e];
        int pos = atomicAdd(&g_cnt[d], 1);
        g_edge[pos] = pack_edge(s, g_dis[s] * g_dis[d]);
    }
}

// per-node: step-invariant aggregates (A_hat x, A_hat 1), initial h, out row 0
__global__ void k_node_pre(const float* __restrict__ x, const float* __restrict__ y,
                           const float* __restrict__ fc1W, const float* __restrict__ fc1b,
                           const float* __restrict__ fc2W, const float* __restrict__ fc2b,
                           float* __restrict__ out, int n) {
    __shared__ float s1W[32], s1b[32], s2W[32 * 26], s2b[26];
    for (int i = threadIdx.x; i < 32; i += blockDim.x) { s1W[i] = fc1W[i]; s1b[i] = fc1b[i]; }
    for (int i = threadIdx.x; i < 32 * 26; i += blockDim.x) s2W[i] = fc2W[i];
    for (int i = threadIdx.x; i < 26; i += blockDim.x) s2b[i] = fc2b[i];
    __syncthreads();
    int stride = gridDim.x * blockDim.x;
    for (int i = blockIdx.x * blockDim.x + threadIdx.x; i < n; i += stride) {
        int beg = g_rowptr[i], end = g_rowptr[i + 1];
        float aone = 0.f, ax = 0.f;
        for (int e = beg; e < end; ++e) {
            unsigned long long v = g_edge[e];
            int c = (int)(unsigned)v;
            float w = __uint_as_float((unsigned)(v >> 32));
            aone += w;
            ax += w * __ldg(&x[c]);
        }
        g_aone[i] = aone;
        g_ax[i] = ax;
        float y0 = y[i];
        out[i] = y0;
        float h0[32];
#pragma unroll
        for (int j = 0; j < 32; j++) h0[j] = fmaxf(fmaf(y0, s1W[j], s1b[j]), 0.f);
        for (int j = 0; j < 26; j++) {
            float s = s2b[j];
#pragma unroll
            for (int k = 0; k < 32; k++) s = fmaf(h0[k], s2W[k * 26 + j], s);
            g_bufA[i * 32 + j] = fmaxf(s, 0.f);
        }
#pragma unroll
        for (int j = 26; j < 32; j++) g_bufA[i * 32 + j] = 0.f;
    }
}

// ---------------- fused GCN conv: warp-per-node, lane = feature ----------------
// MODE 1: hin = [h(26) | x*3 | t*3] via precomputed ax/aone, out 32  (bufA -> bufB)
// MODE 2: 32 -> 32                                                   (bufB -> bufC)
// MODE 3: 32 -> 26 + fused output head fc3/relu/fc4                  (bufC -> bufA)
template <int MODE>
__global__ __launch_bounds__(256)
void k_conv(const float* __restrict__ W, const float* __restrict__ B,
            const float* __restrict__ f3W, const float* __restrict__ f3b,
            const float* __restrict__ f4W, const float* __restrict__ f4b,
            const float* __restrict__ tarr, int trow,
            float* __restrict__ out, int n) {
    __shared__ float sW[1024];
    __shared__ float sB[32];
    __shared__ float sf3W[26 * 32];
    __shared__ float sf3b[32];
    __shared__ float sf4W[32];
    __shared__ float sf4b;

    constexpr int KK  = (MODE == 1) ? 26 : 32;   // shfl-matvec depth
    constexpr int OUT = (MODE == 3) ? 26 : 32;
    constexpr int WSZ = (MODE == 3) ? 32 * 26 : 32 * 32;

    for (int i = threadIdx.x; i < WSZ; i += blockDim.x) sW[i] = W[i];
    for (int i = threadIdx.x; i < OUT; i += blockDim.x) sB[i] = B[i];
    if constexpr (MODE == 3) {
        for (int i = threadIdx.x; i < 26 * 32; i += blockDim.x) sf3W[i] = f3W[i];
        for (int i = threadIdx.x; i < 32; i += blockDim.x) { sf3b[i] = f3b[i]; sf4W[i] = f4W[i]; }
        if (threadIdx.x == 0) sf4b = f4b[0];
    }
    __syncthreads();

    const int lane = threadIdx.x & 31;
    const float* __restrict__ hin  = (MODE == 1) ? g_bufA : ((MODE == 2) ? g_bufB : g_bufC);
    float* __restrict__       hout = (MODE == 1) ? g_bufB : ((MODE == 2) ? g_bufC : g_bufA);

    float wreg[KK];
#pragma unroll
    for (int k = 0; k < KK; k++) wreg[k] = (lane < OUT) ? sW[k * OUT + lane] : 0.f;
    float wx = 0.f, wt = 0.f;
    if constexpr (MODE == 1) {
        wx = sW[26 * 32 + lane] + sW[27 * 32 + lane] + sW[28 * 32 + lane];
        wt = sW[29 * 32 + lane] + sW[30 * 32 + lane] + sW[31 * 32 + lane];
    }
    const float breg = (lane < OUT) ? sB[lane] : 0.f;
    const float tval = (MODE == 1) ? __ldg(&tarr[trow]) : 0.f;

    int wid = (blockIdx.x * blockDim.x + threadIdx.x) >> 5;
    int nw  = (gridDim.x * blockDim.x) >> 5;

    for (int node = wid; node < n; node += nw) {
        int beg = __ldg(&g_rowptr[node]);
        int end = __ldg(&g_rowptr[node + 1]);
        float acc = 0.f;
        int e = beg;
        for (; e + 4 <= end; e += 4) {   // MLP = 4
            unsigned long long v0 = g_edge[e],     v1 = g_edge[e + 1];
            unsigned long long v2 = g_edge[e + 2], v3 = g_edge[e + 3];
            float gg0 = hin[((int)(unsigned)v0) * 32 + lane];
            float gg1 = hin[((int)(unsigned)v1) * 32 + lane];
            float gg2 = hin[((int)(unsigned)v2) * 32 + lane];
            float gg3 = hin[((int)(unsigned)v3) * 32 + lane];
            acc = fmaf(__uint_as_float((unsigned)(v0 >> 32)), gg0, acc);
            acc = fmaf(__uint_as_float((unsigned)(v1 >> 32)), gg1, acc);
            acc = fmaf(__uint_as_float((unsigned)(v2 >> 32)), gg2, acc);
            acc = fmaf(__uint_as_float((unsigned)(v3 >> 32)), gg3, acc);
        }
        for (; e < end; ++e) {
            unsigned long long v = g_edge[e];
            acc = fmaf(__uint_as_float((unsigned)(v >> 32)),
                       hin[((int)(unsigned)v) * 32 + lane], acc);
        }

        // out_j = relu( sum_k agg_k * W[k][j] + b[j] )
        float o = breg;
#pragma unroll
        for (int k = 0; k < KK; k++)
            o = fmaf(__shfl_sync(0xffffffffu, acc, k), wreg[k], o);
        if constexpr (MODE == 1) {
            float axv = __ldg(&g_ax[node]);
            float a1v = __ldg(&g_aone[node]) * tval;
            o = fmaf(axv, wx, o);
            o = fmaf(a1v, wt, o);
        }
        o = fmaxf(o, 0.f);

        if constexpr (MODE != 3) {
            hout[node * 32 + lane] = o;
        } else {
            float h3 = (lane < 26) ? o : 0.f;
            hout[node * 32 + lane] = h3;              // carry for next step
            // fused output head: z = relu(h3 @ fc3 + b3); yy = z @ fc4 + b4
            float z = sf3b[lane];
#pragma unroll
            for (int k = 0; k < 26; k++)
                z = fmaf(__shfl_sync(0xffffffffu, h3, k), sf3W[k * 32 + lane], z);
            z = fmaxf(z, 0.f);
            float p = z * sf4W[lane];
#pragma unroll
            for (int off = 16; off; off >>= 1)
                p += __shfl_xor_sync(0xffffffffu, p, off);
            if (lane == 0) out[(long long)trow * n + node] = p + sf4b;
        }
    }
}

// ---------------- launcher ----------------
extern "C" void kernel_launch(void* const* d_in, const int* in_sizes, int n_in,
                              void* d_out, int out_size) {
    const float* x    = (const float*)d_in[0];
    const float* t    = (const float*)d_in[1];
    const float* y    = (const float*)d_in[2];
    const int*   ei   = (const int*)d_in[3];     // int32 (JAX x64 disabled)
    const float* fc1W = (const float*)d_in[4],  *fc1b = (const float*)d_in[5];
    const float* fc2W = (const float*)d_in[6],  *fc2b = (const float*)d_in[7];
    const float* c1W  = (const float*)d_in[8],  *c1b  = (const float*)d_in[9];
    const float* c2W  = (const float*)d_in[10], *c2b  = (const float*)d_in[11];
    const float* c3W  = (const float*)d_in[12], *c3b  = (const float*)d_in[13];
    const float* fc3W = (const float*)d_in[14], *fc3b = (const float*)d_in[15];
    const float* fc4W = (const float*)d_in[16], *fc4b = (const float*)d_in[17];

    int n = in_sizes[0];          // N
    int T = in_sizes[1];          // timesteps
    int E = in_sizes[3] / 2;      // edges
    float* out = (float*)d_out;

    const int tb = 256;
    k_init<<<(n + tb - 1) / tb, tb>>>(n);
    k_hist<<<(E + tb - 1) / tb, tb>>>(ei, E);
    k_scan<<<1, 1024>>>(n);
    k_selfloop<<<(n + tb - 1) / tb, tb>>>(n);
    k_scatter<<<(E + tb - 1) / tb, tb>>>(ei, E);
    k_node_pre<<<(n + tb - 1) / tb, tb>>>(x, y, fc1W, fc1b, fc2W, fc2b, out, n);

    const int CB = 1536;   // grid-stride: ~8 nodes per warp
    for (int r = 1; r < T; r++) {
        k_conv<1><<<CB, 256>>>(c1W, c1b, nullptr, nullptr, nullptr, nullptr, t, r, out, n);
        k_conv<2><<<CB, 256>>>(c2W, c2b, nullptr, nullptr, nullptr, nullptr, t, r, out, n);
        k_conv<3><<<CB, 256>>>(c3W, c3b, fc3W, fc3b, fc4W, fc4b, t, r, out, n);
    }
}

// round 3
// speedup vs baseline: 1.0766x; 1.0766x over previous
#include <cuda_runtime.h>

#define NN 100000
#define EE 1600000
#define TOTE (NN + EE)

// ---------------- static device scratch (allocation-free, zero-init) ----------------
__device__ int                g_rowptr[NN + 1];
__device__ int                g_cnt[NN];          // histogram; reset by k_scan for next replay
__device__ int                g_cur[NN];          // scatter cursor
__device__ float              g_dis[NN];          // rsqrt(deg)
__device__ float              g_ax[NN];           // (A_hat x)  per node
__device__ float              g_aone[NN];         // (A_hat 1)  per node
__device__ unsigned long long g_edge[TOTE];       // packed {src(int32) | normbits<<32}
__device__ float              g_bufA[NN * 32];    // carry h (26 used, padded)
__device__ float              g_bufB[NN * 32];
__device__ float              g_bufC[NN * 32];

__device__ __forceinline__ unsigned long long pack_edge(int c, float w) {
    return (unsigned long long)(unsigned)c |
           ((unsigned long long)__float_as_uint(w) << 32);
}

// ---------------- preprocessing ----------------
// 1) histogram of edge destinations (g_cnt starts zero: static init / reset by k_scan)
__global__ void k_hist(const int* __restrict__ ei, int E) {
    int e = blockIdx.x * blockDim.x + threadIdx.x;
    if (e < E) atomicAdd(&g_cnt[ei[E + e]], 1);
}

// 2) single-block warp-shuffle exclusive scan; fuses: deg->dis, self-loop edge,
//    cursor init, and resets g_cnt to 0 for the next replay.
__global__ void k_scan(int n) {
    __shared__ int warpsum[32];
    __shared__ int chunkbase;
    const int tid = threadIdx.x, lane = tid & 31, wid = tid >> 5;
    if (tid == 0) chunkbase = 0;
    __syncthreads();
    for (int base = 0; base < n; base += 1024) {
        int i = base + tid;
        int ecnt = (i < n) ? g_cnt[i] : 0;
        if (i < n) g_cnt[i] = 0;                   // reset for next replay
        int v = ecnt + 1;                          // + self-loop
        int s = v;
#pragma unroll
        for (int d = 1; d < 32; d <<= 1) {
            int t = __shfl_up_sync(0xffffffffu, s, d);
            if (lane >= d) s += t;
        }
        if (lane == 31) warpsum[wid] = s;
        __syncthreads();
        if (wid == 0) {
            int ws = warpsum[lane];
#pragma unroll
            for (int d = 1; d < 32; d <<= 1) {
                int t = __shfl_up_sync(0xffffffffu, ws, d);
                if (lane >= d) ws += t;
            }
            warpsum[lane] = ws;
        }
        __syncthreads();
        int excl = chunkbase + s - v + (wid ? warpsum[wid - 1] : 0);
        if (i < n) {
            g_rowptr[i] = excl;
            float dv = rsqrtf((float)v);
            g_dis[i] = dv;
            g_edge[excl] = pack_edge(i, dv * dv);  // self-loop edge first in row
            g_cur[i] = excl + 1;
        }
        __syncthreads();
        if (tid == 0) chunkbase += warpsum[31];
        __syncthreads();
    }
    if (tid == 0) g_rowptr[n] = chunkbase;
}

// 3) scatter edges into CSR rows
__global__ void k_scatter(const int* __restrict__ ei, int E) {
    int e = blockIdx.x * blockDim.x + threadIdx.x;
    if (e < E) {
        int s = ei[e];
        int d = ei[E + e];
        int pos = atomicAdd(&g_cur[d], 1);
        g_edge[pos] = pack_edge(s, g_dis[s] * g_dis[d]);
    }
}

// 4) per-node: step-invariant aggregates (A_hat x, A_hat 1), initial h, out row 0
__global__ void k_node_pre(const float* __restrict__ x, const float* __restrict__ y,
                           const float* __restrict__ fc1W, const float* __restrict__ fc1b,
                           const float* __restrict__ fc2W, const float* __restrict__ fc2b,
                           float* __restrict__ out, int n) {
    __shared__ float s1W[32], s1b[32], s2W[32 * 26], s2b[26];
    for (int i = threadIdx.x; i < 32; i += blockDim.x) { s1W[i] = fc1W[i]; s1b[i] = fc1b[i]; }
    for (int i = threadIdx.x; i < 32 * 26; i += blockDim.x) s2W[i] = fc2W[i];
    for (int i = threadIdx.x; i < 26; i += blockDim.x) s2b[i] = fc2b[i];
    __syncthreads();
    int stride = gridDim.x * blockDim.x;
    for (int i = blockIdx.x * blockDim.x + threadIdx.x; i < n; i += stride) {
        int beg = g_rowptr[i], end = g_rowptr[i + 1];
        float aone = 0.f, ax = 0.f;
        for (int e = beg; e < end; ++e) {
            unsigned long long v = g_edge[e];
            int c = (int)(unsigned)v;
            float w = __uint_as_float((unsigned)(v >> 32));
            aone += w;
            ax += w * __ldg(&x[c]);
        }
        g_aone[i] = aone;
        g_ax[i] = ax;
        float y0 = y[i];
        out[i] = y0;
        float h0[32];
#pragma unroll
        for (int j = 0; j < 32; j++) h0[j] = fmaxf(fmaf(y0, s1W[j], s1b[j]), 0.f);
        for (int j = 0; j < 26; j++) {
            float s = s2b[j];
#pragma unroll
            for (int k = 0; k < 32; k++) s = fmaf(h0[k], s2W[k * 26 + j], s);
            g_bufA[i * 32 + j] = fmaxf(s, 0.f);
        }
#pragma unroll
        for (int j = 26; j < 32; j++) g_bufA[i * 32 + j] = 0.f;
    }
}

// ---------------- fused GCN conv ----------------
// Warp layout: lane = edge_group(lane>>3) x float4_feature(lane&7).
// Per iteration a warp processes 4 edges x 32 features via one LDG.128/lane.
// MODE 1: hin = [h(26) | x*3 | t*3] via precomputed ax/aone, out 32  (bufA -> bufB)
// MODE 2: 32 -> 32                                                   (bufB -> bufC)
// MODE 3: 32 -> 26 + fused output head fc3/relu/fc4                  (bufC -> bufA)
template <int MODE>
__global__ __launch_bounds__(256)
void k_conv(const float* __restrict__ W, const float* __restrict__ B,
            const float* __restrict__ f3W, const float* __restrict__ f3b,
            const float* __restrict__ f4W, const float* __restrict__ f4b,
            const float* __restrict__ tarr, int trow,
            float* __restrict__ out, int n) {
    __shared__ float sW[32 * 32];      // padded: sW[k*32+j], j<OUT valid else 0
    __shared__ float sB[32];
    __shared__ float sf3W[26 * 32];
    __shared__ float sf3b[32];
    __shared__ float sf4W[32];
    __shared__ float sf4b;

    constexpr int KK  = (MODE == 1) ? 26 : 32;   // matvec depth
    constexpr int OUT = (MODE == 3) ? 26 : 32;

    for (int i = threadIdx.x; i < 32 * 32; i += blockDim.x) {
        int k = i >> 5, j = i & 31;
        sW[i] = (j < OUT) ? W[k * OUT + j] : 0.f;
    }
    for (int i = threadIdx.x; i < 32; i += blockDim.x) sB[i] = (i < OUT) ? B[i] : 0.f;
    if constexpr (MODE == 3) {
        for (int i = threadIdx.x; i < 26 * 32; i += blockDim.x) sf3W[i] = f3W[i];
        for (int i = threadIdx.x; i < 32; i += blockDim.x) { sf3b[i] = f3b[i]; sf4W[i] = f4W[i]; }
        if (threadIdx.x == 0) sf4b = f4b[0];
    }
    __syncthreads();

    const int lane = threadIdx.x & 31;
    const int eg   = lane >> 3;     // edge group 0..3
    const int f4   = lane & 7;      // float4 feature chunk 0..7

    const float* __restrict__ hin  = (MODE == 1) ? g_bufA : ((MODE == 2) ? g_bufB : g_bufC);
    float* __restrict__       hout = (MODE == 1) ? g_bufB : ((MODE == 2) ? g_bufC : g_bufA);
    const float4* __restrict__ hin4 = reinterpret_cast<const float4*>(hin);

    float wx = 0.f, wt = 0.f;
    if constexpr (MODE == 1) {
        wx = sW[26 * 32 + lane] + sW[27 * 32 + lane] + sW[28 * 32 + lane];
        wt = sW[29 * 32 + lane] + sW[30 * 32 + lane] + sW[31 * 32 + lane];
    }
    const float breg = sB[lane];
    const float tval = (MODE == 1) ? __ldg(&tarr[trow]) : 0.f;

    int wid = (blockIdx.x * blockDim.x + threadIdx.x) >> 5;
    int nw  = (gridDim.x * blockDim.x) >> 5;

    for (int node = wid; node < n; node += nw) {
        int beg = __ldg(&g_rowptr[node]);
        int end = __ldg(&g_rowptr[node + 1]);

        float4 acc = make_float4(0.f, 0.f, 0.f, 0.f);
#pragma unroll 2
        for (int e = beg; e < end; e += 4) {
            int idx = e + eg;
            int safe = (idx < end) ? idx : (end - 1);
            unsigned long long v = __ldg(&g_edge[safe]);
            float w = (idx < end) ? __uint_as_float((unsigned)(v >> 32)) : 0.f;
            int src = (int)(unsigned)v;
            float4 g = __ldg(&hin4[src * 8 + f4]);
            acc.x = fmaf(w, g.x, acc.x);
            acc.y = fmaf(w, g.y, acc.y);
            acc.z = fmaf(w, g.z, acc.z);
            acc.w = fmaf(w, g.w, acc.w);
        }
        // reduce across the 4 edge groups (xor over bits 3,4 of lane)
#pragma unroll
        for (int off = 8; off <= 16; off <<= 1) {
            acc.x += __shfl_xor_sync(0xffffffffu, acc.x, off);
            acc.y += __shfl_xor_sync(0xffffffffu, acc.y, off);
            acc.z += __shfl_xor_sync(0xffffffffu, acc.z, off);
            acc.w += __shfl_xor_sync(0xffffffffu, acc.w, off);
        }
        // transpose: lane j <- feature j (= comp j&3 of f4-group j>>2, held by lane j>>2)
        int srcl = lane >> 2;
        float a0 = __shfl_sync(0xffffffffu, acc.x, srcl);
        float a1 = __shfl_sync(0xffffffffu, acc.y, srcl);
        float a2 = __shfl_sync(0xffffffffu, acc.z, srcl);
        float a3 = __shfl_sync(0xffffffffu, acc.w, srcl);
        int c = lane & 3;
        float aggv = (c == 0) ? a0 : (c == 1) ? a1 : (c == 2) ? a2 : a3;

        // out_j = relu( sum_k agg_k * W[k][j] + b[j] )
        float o = breg;
#pragma unroll
        for (int k = 0; k < KK; k++)
            o = fmaf(__shfl_sync(0xffffffffu, aggv, k), sW[k * 32 + lane], o);
        if constexpr (MODE == 1) {
            o = fmaf(__ldg(&g_ax[node]), wx, o);
            o = fmaf(__ldg(&g_aone[node]) * tval, wt, o);
        }
        o = fmaxf(o, 0.f);

        if constexpr (MODE != 3) {
            hout[node * 32 + lane] = o;
        } else {
            float h3 = (lane < 26) ? o : 0.f;
            hout[node * 32 + lane] = h3;              // carry for next step
            float z = sf3b[lane];
#pragma unroll
            for (int k = 0; k < 26; k++)
                z = fmaf(__shfl_sync(0xffffffffu, h3, k), sf3W[k * 32 + lane], z);
            z = fmaxf(z, 0.f);
            float p = z * sf4W[lane];
#pragma unroll
            for (int off = 16; off; off >>= 1)
                p += __shfl_xor_sync(0xffffffffu, p, off);
            if (lane == 0) out[(long long)trow * n + node] = p + sf4b;
        }
    }
}

// ---------------- launcher ----------------
extern "C" void kernel_launch(void* const* d_in, const int* in_sizes, int n_in,
                              void* d_out, int out_size) {
    const float* x    = (const float*)d_in[0];
    const float* t    = (const float*)d_in[1];
    const float* y    = (const float*)d_in[2];
    const int*   ei   = (const int*)d_in[3];     // int32 (JAX x64 disabled)
    const float* fc1W = (const float*)d_in[4],  *fc1b = (const float*)d_in[5];
    const float* fc2W = (const float*)d_in[6],  *fc2b = (const float*)d_in[7];
    const float* c1W  = (const float*)d_in[8],  *c1b  = (const float*)d_in[9];
    const float* c2W  = (const float*)d_in[10], *c2b  = (const float*)d_in[11];
    const float* c3W  = (const float*)d_in[12], *c3b  = (const float*)d_in[13];
    const float* fc3W = (const float*)d_in[14], *fc3b = (const float*)d_in[15];
    const float* fc4W = (const float*)d_in[16], *fc4b = (const float*)d_in[17];

    int n = in_sizes[0];          // N
    int T = in_sizes[1];          // timesteps
    int E = in_sizes[3] / 2;      // edges
    float* out = (float*)d_out;

    const int tb = 256;
    k_hist<<<(E + tb - 1) / tb, tb>>>(ei, E);
    k_scan<<<1, 1024>>>(n);
    k_scatter<<<(E + tb - 1) / tb, tb>>>(ei, E);
    k_node_pre<<<(n + tb - 1) / tb, tb>>>(x, y, fc1W, fc1b, fc2W, fc2b, out, n);

    const int CB = 888;   // 148 SMs x 6 blocks
    for (int r = 1; r < T; r++) {
        k_conv<1><<<CB, 256>>>(c1W, c1b, nullptr, nullptr, nullptr, nullptr, t, r, out, n);
        k_conv<2><<<CB, 256>>>(c2W, c2b, nullptr, nullptr, nullptr, nullptr, t, r, out, n);
        k_conv<3><<<CB, 256>>>(c3W, c3b, fc3W, fc3b, fc4W, fc4b, t, r, out, n);
    }
}

// round 4
// speedup vs baseline: 1.2331x; 1.1454x over previous
#include <cuda_runtime.h>
#include <cuda_fp16.h>

#define NN 100000
#define EE 1600000
#define TOTE (NN + EE)

// ---------------- static device scratch (allocation-free, zero-init) ----------------
__device__ int                g_rowptr[NN + 1];
__device__ int                g_cnt[NN];          // histogram; reset by k_scan for next replay
__device__ int                g_cur[NN];          // scatter cursor
__device__ float              g_dis[NN];          // rsqrt(deg)
__device__ float2             g_axw[NN];          // {A_hat x, A_hat 1} per node (atomic-built)
__device__ unsigned long long g_edge[TOTE];       // packed {src(int32) | normbits<<32}
__device__ uint2              g_bufA[NN * 8];     // fp16 feature rows, 64B/node
__device__ uint2              g_bufB[NN * 8];
__device__ uint2              g_bufC[NN * 8];

__device__ __forceinline__ unsigned long long pack_edge(int c, float w) {
    return (unsigned long long)(unsigned)c |
           ((unsigned long long)__float_as_uint(w) << 32);
}

// ---------------- preprocessing (3 launches so conv1 is launch #4) ----------------
// 1) histogram of edge destinations
__global__ void k_hist(const int* __restrict__ ei, int E) {
    int e = blockIdx.x * blockDim.x + threadIdx.x;
    if (e < E) atomicAdd(&g_cnt[ei[E + e]], 1);
}

// 2) single-block warp-shuffle exclusive scan; fuses: deg->dis, self-loop edge,
//    cursor init, self-loop seed of g_axw, and resets g_cnt for next replay.
__global__ void k_scan(const float* __restrict__ x, int n) {
    __shared__ int warpsum[32];
    __shared__ int chunkbase;
    const int tid = threadIdx.x, lane = tid & 31, wid = tid >> 5;
    if (tid == 0) chunkbase = 0;
    __syncthreads();
    for (int base = 0; base < n; base += 1024) {
        int i = base + tid;
        int ecnt = (i < n) ? g_cnt[i] : 0;
        if (i < n) g_cnt[i] = 0;                   // reset for next replay
        int v = ecnt + 1;                          // + self-loop
        int s = v;
#pragma unroll
        for (int d = 1; d < 32; d <<= 1) {
            int t = __shfl_up_sync(0xffffffffu, s, d);
            if (lane >= d) s += t;
        }
        if (lane == 31) warpsum[wid] = s;
        __syncthreads();
        if (wid == 0) {
            int ws = warpsum[lane];
#pragma unroll
            for (int d = 1; d < 32; d <<= 1) {
                int t = __shfl_up_sync(0xffffffffu, ws, d);
                if (lane >= d) ws += t;
            }
            warpsum[lane] = ws;
        }
        __syncthreads();
        int excl = chunkbase + s - v + (wid ? warpsum[wid - 1] : 0);
        if (i < n) {
            g_rowptr[i] = excl;
            float dv = rsqrtf((float)v);
            float dvdv = dv * dv;
            g_dis[i] = dv;
            g_edge[excl] = pack_edge(i, dvdv);     // self-loop edge first in row
            g_cur[i] = excl + 1;
            g_axw[i] = make_float2(dvdv * __ldg(&x[i]), dvdv);  // self-loop seed
        }
        __syncthreads();
        if (tid == 0) chunkbase += warpsum[31];
        __syncthreads();
    }
    if (tid == 0) g_rowptr[n] = chunkbase;
}

// 3) fused: edge scatter (+atomic A_hat x / A_hat 1) AND per-node MLP init.
//    Threads [0,n): node MLP; threads [n, n+E): edge scatter. No inter-dependency.
__global__ void k_scatter_pre(const int* __restrict__ ei, int E,
                              const float* __restrict__ x, const float* __restrict__ y,
                              const float* __restrict__ fc1W, const float* __restrict__ fc1b,
                              const float* __restrict__ fc2W, const float* __restrict__ fc2b,
                              float* __restrict__ out, int n) {
    __shared__ float s1W[32], s1b[32], s2W[32 * 26], s2b[26];
    for (int i = threadIdx.x; i < 32; i += blockDim.x) { s1W[i] = fc1W[i]; s1b[i] = fc1b[i]; }
    for (int i = threadIdx.x; i < 32 * 26; i += blockDim.x) s2W[i] = fc2W[i];
    for (int i = threadIdx.x; i < 26; i += blockDim.x) s2b[i] = fc2b[i];
    __syncthreads();
    int total = n + E;
    int stride = gridDim.x * blockDim.x;
    for (int g = blockIdx.x * blockDim.x + threadIdx.x; g < total; g += stride) {
        if (g < n) {
            int i = g;
            float y0 = y[i];
            out[i] = y0;
            float h0[32];
#pragma unroll
            for (int j = 0; j < 32; j++) h0[j] = fmaxf(fmaf(y0, s1W[j], s1b[j]), 0.f);
            __half hrow[32];
            for (int j = 0; j < 26; j++) {
                float s = s2b[j];
#pragma unroll
                for (int k = 0; k < 32; k++) s = fmaf(h0[k], s2W[k * 26 + j], s);
                hrow[j] = __float2half(fmaxf(s, 0.f));
            }
#pragma unroll
            for (int j = 26; j < 32; j++) hrow[j] = __float2half(0.f);
            const uint2* hr = reinterpret_cast<const uint2*>(hrow);
#pragma unroll
            for (int q = 0; q < 8; q++) g_bufA[i * 8 + q] = hr[q];
        } else {
            int e = g - n;
            int s = ei[e];
            int d = ei[E + e];
            float w = g_dis[s] * g_dis[d];
            int pos = atomicAdd(&g_cur[d], 1);
            g_edge[pos] = pack_edge(s, w);
            atomicAdd(&g_axw[d].x, w * __ldg(&x[s]));
            atomicAdd(&g_axw[d].y, w);
        }
    }
}

// ---------------- fused GCN conv (fp16 features, fp32 accumulate) ----------------
// Warp layout: lane = edge_group(lane>>3) x uint2_chunk(lane&7).
// Per iteration a warp processes 4 edges x 32 fp16 features via one LDG.64/lane.
// MODE 1: hin = [h(26) | x*3 | t*3] via precomputed axw, out 32   (bufA -> bufB)
// MODE 2: 32 -> 32                                                 (bufB -> bufC)
// MODE 3: 32 -> 26 + fused output head fc3/relu/fc4                (bufC -> bufA)
template <int MODE>
__global__ __launch_bounds__(256)
void k_conv(const float* __restrict__ W, const float* __restrict__ B,
            const float* __restrict__ f3W, const float* __restrict__ f3b,
            const float* __restrict__ f4W, const float* __restrict__ f4b,
            const float* __restrict__ tarr, int trow,
            float* __restrict__ out, int n) {
    __shared__ float sW[32 * 32];      // padded: sW[k*32+j], j<OUT valid else 0
    __shared__ float sB[32];
    __shared__ float sf3W[26 * 32];
    __shared__ float sf3b[32];
    __shared__ float sf4W[32];
    __shared__ float sf4b;

    constexpr int KK  = (MODE == 1) ? 26 : 32;   // matvec depth
    constexpr int OUT = (MODE == 3) ? 26 : 32;

    for (int i = threadIdx.x; i < 32 * 32; i += blockDim.x) {
        int k = i >> 5, j = i & 31;
        sW[i] = (j < OUT) ? W[k * OUT + j] : 0.f;
    }
    for (int i = threadIdx.x; i < 32; i += blockDim.x) sB[i] = (i < OUT) ? B[i] : 0.f;
    if constexpr (MODE == 3) {
        for (int i = threadIdx.x; i < 26 * 32; i += blockDim.x) sf3W[i] = f3W[i];
        for (int i = threadIdx.x; i < 32; i += blockDim.x) { sf3b[i] = f3b[i]; sf4W[i] = f4W[i]; }
        if (threadIdx.x == 0) sf4b = f4b[0];
    }
    __syncthreads();

    const int lane = threadIdx.x & 31;
    const int eg   = lane >> 3;     // edge group 0..3
    const int f    = lane & 7;      // uint2 chunk 0..7 (features 4f..4f+3)

    const uint2* __restrict__ hin  = (MODE == 1) ? g_bufA : ((MODE == 2) ? g_bufB : g_bufC);
    uint2* __restrict__       hout = (MODE == 1) ? g_bufB : ((MODE == 2) ? g_bufC : g_bufA);
    __half2* __restrict__     hout2 = reinterpret_cast<__half2*>(hout);

    float wx = 0.f, wt = 0.f;
    if constexpr (MODE == 1) {
        wx = sW[26 * 32 + lane] + sW[27 * 32 + lane] + sW[28 * 32 + lane];
        wt = sW[29 * 32 + lane] + sW[30 * 32 + lane] + sW[31 * 32 + lane];
    }
    const float breg = sB[lane];
    const float tval = (MODE == 1) ? __ldg(&tarr[trow]) : 0.f;

    int wid = (blockIdx.x * blockDim.x + threadIdx.x) >> 5;
    int nw  = (gridDim.x * blockDim.x) >> 5;

    for (int node = wid; node < n; node += nw) {
        int beg = __ldg(&g_rowptr[node]);
        int end = __ldg(&g_rowptr[node + 1]);

        float4 acc = make_float4(0.f, 0.f, 0.f, 0.f);
#pragma unroll 2
        for (int e = beg; e < end; e += 4) {
            int idx = e + eg;
            int safe = (idx < end) ? idx : (end - 1);
            unsigned long long v = __ldg(&g_edge[safe]);
            float w = (idx < end) ? __uint_as_float((unsigned)(v >> 32)) : 0.f;
            int src = (int)(unsigned)v;
            uint2 raw = __ldg(&hin[src * 8 + f]);
            float2 p0 = __half22float2(*reinterpret_cast<const __half2*>(&raw.x));
            float2 p1 = __half22float2(*reinterpret_cast<const __half2*>(&raw.y));
            acc.x = fmaf(w, p0.x, acc.x);
            acc.y = fmaf(w, p0.y, acc.y);
            acc.z = fmaf(w, p1.x, acc.z);
            acc.w = fmaf(w, p1.y, acc.w);
        }
        // reduce across the 4 edge groups (xor over bits 3,4 of lane)
#pragma unroll
        for (int off = 8; off <= 16; off <<= 1) {
            acc.x += __shfl_xor_sync(0xffffffffu, acc.x, off);
            acc.y += __shfl_xor_sync(0xffffffffu, acc.y, off);
            acc.z += __shfl_xor_sync(0xffffffffu, acc.z, off);
            acc.w += __shfl_xor_sync(0xffffffffu, acc.w, off);
        }
        // transpose: lane j <- feature j (= comp j&3 of chunk j>>2, held by lane j>>2)
        int srcl = lane >> 2;
        float a0 = __shfl_sync(0xffffffffu, acc.x, srcl);
        float a1 = __shfl_sync(0xffffffffu, acc.y, srcl);
        float a2 = __shfl_sync(0xffffffffu, acc.z, srcl);
        float a3 = __shfl_sync(0xffffffffu, acc.w, srcl);
        int c = lane & 3;
        float aggv = (c == 0) ? a0 : (c == 1) ? a1 : (c == 2) ? a2 : a3;

        // out_j = relu( sum_k agg_k * W[k][j] + b[j] )
        float o = breg;
#pragma unroll
        for (int k = 0; k < KK; k++)
            o = fmaf(__shfl_sync(0xffffffffu, aggv, k), sW[k * 32 + lane], o);
        if constexpr (MODE == 1) {
            float2 axw = __ldg(&g_axw[node]);
            o = fmaf(axw.x, wx, o);
            o = fmaf(axw.y * tval, wt, o);
        }
        o = fmaxf(o, 0.f);

        // pack pairs of lanes -> half2, 16 lanes store 4B each (64B row)
        float o_hi = __shfl_down_sync(0xffffffffu, o, 1);
        if ((lane & 1) == 0)
            hout2[node * 16 + (lane >> 1)] = __floats2half2_rn(o, o_hi);

        if constexpr (MODE == 3) {
            float h3 = o;   // lanes >=26 are zero by construction (padded W/B)
            float z = sf3b[lane];
#pragma unroll
            for (int k = 0; k < 26; k++)
                z = fmaf(__shfl_sync(0xffffffffu, h3, k), sf3W[k * 32 + lane], z);
            z = fmaxf(z, 0.f);
            float p = z * sf4W[lane];
#pragma unroll
            for (int off = 16; off; off >>= 1)
                p += __shfl_xor_sync(0xffffffffu, p, off);
            if (lane == 0) out[(long long)trow * n + node] = p + sf4b;
        }
    }
}

// ---------------- launcher ----------------
extern "C" void kernel_launch(void* const* d_in, const int* in_sizes, int n_in,
                              void* d_out, int out_size) {
    const float* x    = (const float*)d_in[0];
    const float* t    = (const float*)d_in[1];
    const float* y    = (const float*)d_in[2];
    const int*   ei   = (const int*)d_in[3];     // int32 (JAX x64 disabled)
    const float* fc1W = (const float*)d_in[4],  *fc1b = (const float*)d_in[5];
    const float* fc2W = (const float*)d_in[6],  *fc2b = (const float*)d_in[7];
    const float* c1W  = (const float*)d_in[8],  *c1b  = (const float*)d_in[9];
    const float* c2W  = (const float*)d_in[10], *c2b  = (const float*)d_in[11];
    const float* c3W  = (const float*)d_in[12], *c3b  = (const float*)d_in[13];
    const float* fc3W = (const float*)d_in[14], *fc3b = (const float*)d_in[15];
    const float* fc4W = (const float*)d_in[16], *fc4b = (const float*)d_in[17];

    int n = in_sizes[0];          // N
    int T = in_sizes[1];          // timesteps
    int E = in_sizes[3] / 2;      // edges
    float* out = (float*)d_out;

    const int tb = 256;
    k_hist<<<(E + tb - 1) / tb, tb>>>(ei, E);                      // launch 1
    k_scan<<<1, 1024>>>(x, n);                                     // launch 2
    k_scatter_pre<<<(n + E + tb - 1) / tb, tb>>>(ei, E, x, y,      // launch 3
                                                 fc1W, fc1b, fc2W, fc2b, out, n);

    const int CB = 1184;   // 148 SMs x 8 blocks
    for (int r = 1; r < T; r++) {                                  // launch 4 = conv1 (profiled)
        k_conv<1><<<CB, 256>>>(c1W, c1b, nullptr, nullptr, nullptr, nullptr, t, r, out, n);
        k_conv<2><<<CB, 256>>>(c2W, c2b, nullptr, nullptr, nullptr, nullptr, t, r, out, n);
        k_conv<3><<<CB, 256>>>(c3W, c3b, fc3W, fc3b, fc4W, fc4b, t, r, out, n);
    }
}